// round 6
// baseline (speedup 1.0000x reference)
#include <cuda_runtime.h>
#include <cstdint>

#define H   32
#define TPB 128

typedef unsigned long long u64;

// ---------- packed f32x2 helpers ----------
__device__ __forceinline__ u64 pack2(float lo, float hi) {
    u64 r; asm("mov.b64 %0, {%1, %2};" : "=l"(r) : "f"(lo), "f"(hi)); return r;
}
__device__ __forceinline__ void unpack2(u64 v, float& lo, float& hi) {
    asm("mov.b64 {%0, %1}, %2;" : "=f"(lo), "=f"(hi) : "l"(v));
}
__device__ __forceinline__ u64 ffma2(u64 a, u64 b, u64 c) {
    u64 d; asm("fma.rn.f32x2 %0, %1, %2, %3;" : "=l"(d) : "l"(a), "l"(b), "l"(c)); return d;
}
__device__ __forceinline__ u64 fmul2(u64 a, u64 b) {
    u64 d; asm("mul.rn.f32x2 %0, %1, %2;" : "=l"(d) : "l"(a), "l"(b)); return d;
}
__device__ __forceinline__ u64 fadd2(u64 a, u64 b) {
    u64 d; asm("add.rn.f32x2 %0, %1, %2;" : "=l"(d) : "l"(a), "l"(b)); return d;
}
__device__ __forceinline__ float ex2f(float x) {
    float r; asm("ex2.approx.f32 %0, %1;" : "=f"(r) : "f"(x)); return r;
}
__device__ __forceinline__ float rcpf(float x) {
    float r; asm("rcp.approx.f32 %0, %1;" : "=f"(r) : "f"(x)); return r;
}

// tanh on a packed pair: tanh(x) = 1 - 2/(1 + exp(2x)); exp(2x)=ex2(x*2log2e)
// max abs err ~1e-6 (vs ~5e-4 for tanh.approx) — safe for the 1e-3 gate.
__device__ __forceinline__ u64 tanh2(u64 v) {
    const u64 C2   = pack2(2.885390081777927f, 2.885390081777927f);
    const u64 ONE2 = pack2(1.0f, 1.0f);
    const u64 NG2  = pack2(-2.0f, -2.0f);
    u64 m = fmul2(v, C2);
    float mx, my; unpack2(m, mx, my);
    u64 e = pack2(ex2f(mx), ex2f(my));
    u64 t = fadd2(e, ONE2);
    float tx, ty; unpack2(t, tx, ty);
    u64 r = pack2(rcpf(tx), rcpf(ty));
    return ffma2(NG2, r, ONE2);
}

__device__ __forceinline__ u64 pairAB(float a, float b) {
    return ((u64)__float_as_uint(b) << 32) | (u64)__float_as_uint(a);
}

// Lane packing: lo half = d-network, hi half = o-network (same x input).
__global__ void __launch_bounds__(TPB)
damping_kernel(const float* __restrict__ x,
               const float* __restrict__ wd1, const float* __restrict__ wd2,
               const float* __restrict__ wd3, const float* __restrict__ wo1,
               const float* __restrict__ wo2, const float* __restrict__ wo3,
               const float* __restrict__ bd1, const float* __restrict__ bd2,
               const float* __restrict__ bd3, const float* __restrict__ bo1,
               const float* __restrict__ bo2, const float* __restrict__ bo3,
               float* __restrict__ out, int nRows)
{
    __shared__ u64 s_w2[H * H];          // {wd2[j][k], wo2[j][k]}
    __shared__ u64 s_w1[2 * H];          // {wd1[i][k], wo1[i][k]}
    __shared__ u64 s_b1[H], s_b2[H];     // {bd*, bo*}
    __shared__ u64 s_w3a[H];             // {wd3[j][0], wo3[j][0]}
    __shared__ u64 s_w3b[H];             // {wd3[j][1], 0}
    __shared__ u64 s_p0, s_q0;           // {bd3[0], bo3[0]}, {bd3[1], 0}

    for (int i = threadIdx.x; i < H * H; i += TPB)
        s_w2[i] = pairAB(wd2[i], wo2[i]);
    for (int i = threadIdx.x; i < 2 * H; i += TPB)
        s_w1[i] = pairAB(wd1[i], wo1[i]);
    for (int i = threadIdx.x; i < H; i += TPB) {
        s_b1[i]  = pairAB(bd1[i], bo1[i]);
        s_b2[i]  = pairAB(bd2[i], bo2[i]);
        s_w3a[i] = pairAB(wd3[2 * i], wo3[i]);
        s_w3b[i] = pairAB(wd3[2 * i + 1], 0.0f);
    }
    if (threadIdx.x == 0) {
        s_p0 = pairAB(bd3[0], bo3[0]);
        s_q0 = pairAB(bd3[1], 0.0f);
    }
    __syncthreads();

    int row = blockIdx.x * TPB + threadIdx.x;
    if (row >= nRows) return;

    float2 xv = *reinterpret_cast<const float2*>(x + 2 * (size_t)row);
    u64 X0 = pairAB(xv.x, xv.x);
    u64 X1 = pairAB(xv.y, xv.y);

    // ---- layer 1: h[k] = tanh(x0*w1[0][k] + x1*w1[1][k] + b1[k]) (both nets)
    u64 h[H];
    #pragma unroll
    for (int k = 0; k < H; k++)
        h[k] = tanh2(ffma2(X1, s_w1[H + k], ffma2(X0, s_w1[k], s_b1[k])));

    // ---- layer 2 + layer 3 fused: never materialize g[32].
    // P accumulates {d3[0], o3}; Q accumulates {d3[1], junk}.
    u64 P = s_p0, Q = s_q0;
    #pragma unroll
    for (int kb = 0; kb < H; kb += 4) {
        u64 a0 = s_b2[kb], a1 = s_b2[kb + 1], a2 = s_b2[kb + 2], a3 = s_b2[kb + 3];
        #pragma unroll
        for (int j = 0; j < H; j++) {
            u64 hj = h[j];
            const ulonglong2* wr = reinterpret_cast<const ulonglong2*>(s_w2 + j * H + kb);
            ulonglong2 w01 = wr[0];
            ulonglong2 w23 = wr[1];
            a0 = ffma2(hj, w01.x, a0);
            a1 = ffma2(hj, w01.y, a1);
            a2 = ffma2(hj, w23.x, a2);
            a3 = ffma2(hj, w23.y, a3);
        }
        a0 = tanh2(a0); a1 = tanh2(a1); a2 = tanh2(a2); a3 = tanh2(a3);
        P = ffma2(a0, s_w3a[kb],     P);  Q = ffma2(a0, s_w3b[kb],     Q);
        P = ffma2(a1, s_w3a[kb + 1], P);  Q = ffma2(a1, s_w3b[kb + 1], Q);
        P = ffma2(a2, s_w3a[kb + 2], P);  Q = ffma2(a2, s_w3b[kb + 2], Q);
        P = ffma2(a3, s_w3a[kb + 3], P);  Q = ffma2(a3, s_w3b[kb + 3], Q);
    }

    float d30, o3v, d31, junk;
    unpack2(P, d30, o3v);
    unpack2(Q, d31, junk);

    // ---- epilogue
    float a = (fmaxf(d30, 0.f) + 0.001f) * xv.x;
    float b = (fmaxf(d31, 0.f) + 0.001f) * xv.y;
    float c = o3v;

    float2 ov;
    ov.x = a * a * xv.x + a * c * xv.y;
    ov.y = a * c * xv.x + (c * c + b * b) * xv.y;
    *reinterpret_cast<float2*>(out + 2 * (size_t)row) = ov;
}

extern "C" void kernel_launch(void* const* d_in, const int* in_sizes, int n_in,
                              void* d_out, int out_size)
{
    const float* x   = (const float*)d_in[0];
    const float* wd1 = (const float*)d_in[1];
    const float* wd2 = (const float*)d_in[2];
    const float* wd3 = (const float*)d_in[3];
    const float* wo1 = (const float*)d_in[4];
    const float* wo2 = (const float*)d_in[5];
    const float* wo3 = (const float*)d_in[6];
    const float* bd1 = (const float*)d_in[7];
    const float* bd2 = (const float*)d_in[8];
    const float* bd3 = (const float*)d_in[9];
    const float* bo1 = (const float*)d_in[10];
    const float* bo2 = (const float*)d_in[11];
    const float* bo3 = (const float*)d_in[12];
    float* out = (float*)d_out;

    int nRows  = in_sizes[0] / 2;   // x is (B, 2)
    int blocks = (nRows + TPB - 1) / TPB;

    damping_kernel<<<blocks, TPB>>>(x, wd1, wd2, wd3, wo1, wo2, wo3,
                                    bd1, bd2, bd3, bo1, bo2, bo3,
                                    out, nRows);
}

// round 7
// speedup vs baseline: 1.0573x; 1.0573x over previous
#include <cuda_runtime.h>
#include <cstdint>

#define H   32
#define TPB 128

typedef unsigned long long u64;

// ---------- packed f32x2 helpers ----------
__device__ __forceinline__ u64 pack2(float lo, float hi) {
    u64 r; asm("mov.b64 %0, {%1, %2};" : "=l"(r) : "f"(lo), "f"(hi)); return r;
}
__device__ __forceinline__ void unpack2(u64 v, float& lo, float& hi) {
    asm("mov.b64 {%0, %1}, %2;" : "=f"(lo), "=f"(hi) : "l"(v));
}
__device__ __forceinline__ u64 ffma2(u64 a, u64 b, u64 c) {
    u64 d; asm("fma.rn.f32x2 %0, %1, %2, %3;" : "=l"(d) : "l"(a), "l"(b), "l"(c)); return d;
}
__device__ __forceinline__ u64 fmul2(u64 a, u64 b) {
    u64 d; asm("mul.rn.f32x2 %0, %1, %2;" : "=l"(d) : "l"(a), "l"(b)); return d;
}
__device__ __forceinline__ u64 fadd2(u64 a, u64 b) {
    u64 d; asm("add.rn.f32x2 %0, %1, %2;" : "=l"(d) : "l"(a), "l"(b)); return d;
}
__device__ __forceinline__ float ex2f(float x) {
    float r; asm("ex2.approx.f32 %0, %1;" : "=f"(r) : "f"(x)); return r;
}
__device__ __forceinline__ float rcpf(float x) {
    float r; asm("rcp.approx.f32 %0, %1;" : "=f"(r) : "f"(x)); return r;
}

// tanh(x) = 1 - 2/(1 + exp(2x)); exp(2x)=ex2(x*2log2e). Abs err ~1e-6.
__device__ __forceinline__ u64 tanh2(u64 v) {
    const u64 C2   = pack2(2.885390081777927f, 2.885390081777927f);
    const u64 ONE2 = pack2(1.0f, 1.0f);
    const u64 NG2  = pack2(-2.0f, -2.0f);
    u64 m = fmul2(v, C2);
    float mx, my; unpack2(m, mx, my);
    u64 e = pack2(ex2f(mx), ex2f(my));
    u64 t = fadd2(e, ONE2);
    float tx, ty; unpack2(t, tx, ty);
    u64 r = pack2(rcpf(tx), rcpf(ty));
    return ffma2(NG2, r, ONE2);
}

__device__ __forceinline__ u64 pairAB(float a, float b) {
    return ((u64)__float_as_uint(b) << 32) | (u64)__float_as_uint(a);
}

// Lane packing: lo half = d-network, hi half = o-network.
// Each thread processes TWO rows so every weight LDS feeds 4 FFMA2.
__global__ void __launch_bounds__(TPB)
damping_kernel(const float* __restrict__ x,
               const float* __restrict__ wd1, const float* __restrict__ wd2,
               const float* __restrict__ wd3, const float* __restrict__ wo1,
               const float* __restrict__ wo2, const float* __restrict__ wo3,
               const float* __restrict__ bd1, const float* __restrict__ bd2,
               const float* __restrict__ bd3, const float* __restrict__ bo1,
               const float* __restrict__ bo2, const float* __restrict__ bo3,
               float* __restrict__ out, int nPairs)
{
    __shared__ u64 s_w2[H * H];          // {wd2[j][k], wo2[j][k]}
    __shared__ u64 s_w1[2 * H];          // {wd1[i][k], wo1[i][k]}
    __shared__ u64 s_b1[H], s_b2[H];     // {bd*, bo*}
    __shared__ u64 s_w3a[H];             // {wd3[j][0], wo3[j][0]}
    __shared__ u64 s_w3b[H];             // {wd3[j][1], 0}
    __shared__ u64 s_p0, s_q0;           // {bd3[0], bo3[0]}, {bd3[1], 0}

    for (int i = threadIdx.x; i < H * H; i += TPB)
        s_w2[i] = pairAB(wd2[i], wo2[i]);
    for (int i = threadIdx.x; i < 2 * H; i += TPB)
        s_w1[i] = pairAB(wd1[i], wo1[i]);
    for (int i = threadIdx.x; i < H; i += TPB) {
        s_b1[i]  = pairAB(bd1[i], bo1[i]);
        s_b2[i]  = pairAB(bd2[i], bo2[i]);
        s_w3a[i] = pairAB(wd3[2 * i], wo3[i]);
        s_w3b[i] = pairAB(wd3[2 * i + 1], 0.0f);
    }
    if (threadIdx.x == 0) {
        s_p0 = pairAB(bd3[0], bo3[0]);
        s_q0 = pairAB(bd3[1], 0.0f);
    }
    __syncthreads();

    int pair = blockIdx.x * TPB + threadIdx.x;   // rows 2*pair, 2*pair+1
    if (pair >= nPairs) return;

    // x for 2 rows: {x0_r0, x1_r0, x0_r1, x1_r1}
    float4 xv = *reinterpret_cast<const float4*>(x + 4 * (size_t)pair);
    u64 X0a = pairAB(xv.x, xv.x), X1a = pairAB(xv.y, xv.y);
    u64 X0b = pairAB(xv.z, xv.z), X1b = pairAB(xv.w, xv.w);

    // ---- layer 1 (both rows, both nets packed per lane)
    u64 ha[H], hb[H];
    #pragma unroll
    for (int k = 0; k < H; k++) {
        u64 w0 = s_w1[k], w1 = s_w1[H + k], b = s_b1[k];
        ha[k] = tanh2(ffma2(X1a, w1, ffma2(X0a, w0, b)));
        hb[k] = tanh2(ffma2(X1b, w1, ffma2(X0b, w0, b)));
    }

    // ---- layer 2 + 3 fused; 8 accumulator chains (4 outputs x 2 rows)
    u64 Pa = s_p0, Qa = s_q0, Pb = s_p0, Qb = s_q0;
    #pragma unroll
    for (int kb = 0; kb < H; kb += 4) {
        u64 a0 = s_b2[kb], a1 = s_b2[kb + 1], a2 = s_b2[kb + 2], a3 = s_b2[kb + 3];
        u64 c0 = a0, c1 = a1, c2 = a2, c3 = a3;
        #pragma unroll
        for (int j = 0; j < H; j++) {
            const ulonglong2* wr = reinterpret_cast<const ulonglong2*>(s_w2 + j * H + kb);
            ulonglong2 w01 = wr[0];
            ulonglong2 w23 = wr[1];
            u64 hja = ha[j], hjb = hb[j];
            a0 = ffma2(hja, w01.x, a0);  c0 = ffma2(hjb, w01.x, c0);
            a1 = ffma2(hja, w01.y, a1);  c1 = ffma2(hjb, w01.y, c1);
            a2 = ffma2(hja, w23.x, a2);  c2 = ffma2(hjb, w23.x, c2);
            a3 = ffma2(hja, w23.y, a3);  c3 = ffma2(hjb, w23.y, c3);
        }
        a0 = tanh2(a0); a1 = tanh2(a1); a2 = tanh2(a2); a3 = tanh2(a3);
        c0 = tanh2(c0); c1 = tanh2(c1); c2 = tanh2(c2); c3 = tanh2(c3);
        u64 w3a0 = s_w3a[kb],     w3b0 = s_w3b[kb];
        u64 w3a1 = s_w3a[kb + 1], w3b1 = s_w3b[kb + 1];
        u64 w3a2 = s_w3a[kb + 2], w3b2 = s_w3b[kb + 2];
        u64 w3a3 = s_w3a[kb + 3], w3b3 = s_w3b[kb + 3];
        Pa = ffma2(a0, w3a0, Pa);  Qa = ffma2(a0, w3b0, Qa);
        Pb = ffma2(c0, w3a0, Pb);  Qb = ffma2(c0, w3b0, Qb);
        Pa = ffma2(a1, w3a1, Pa);  Qa = ffma2(a1, w3b1, Qa);
        Pb = ffma2(c1, w3a1, Pb);  Qb = ffma2(c1, w3b1, Qb);
        Pa = ffma2(a2, w3a2, Pa);  Qa = ffma2(a2, w3b2, Qa);
        Pb = ffma2(c2, w3a2, Pb);  Qb = ffma2(c2, w3b2, Qb);
        Pa = ffma2(a3, w3a3, Pa);  Qa = ffma2(a3, w3b3, Qa);
        Pb = ffma2(c3, w3a3, Pb);  Qb = ffma2(c3, w3b3, Qb);
    }

    // ---- epilogue, row a
    float d30, o3v, d31, junk;
    unpack2(Pa, d30, o3v);
    unpack2(Qa, d31, junk);
    float aa = (fmaxf(d30, 0.f) + 0.001f) * xv.x;
    float bb = (fmaxf(d31, 0.f) + 0.001f) * xv.y;
    float cc = o3v;
    float4 ov;
    ov.x = aa * aa * xv.x + aa * cc * xv.y;
    ov.y = aa * cc * xv.x + (cc * cc + bb * bb) * xv.y;

    // ---- epilogue, row b
    unpack2(Pb, d30, o3v);
    unpack2(Qb, d31, junk);
    aa = (fmaxf(d30, 0.f) + 0.001f) * xv.z;
    bb = (fmaxf(d31, 0.f) + 0.001f) * xv.w;
    cc = o3v;
    ov.z = aa * aa * xv.z + aa * cc * xv.w;
    ov.w = aa * cc * xv.z + (cc * cc + bb * bb) * xv.w;

    *reinterpret_cast<float4*>(out + 4 * (size_t)pair) = ov;
}

extern "C" void kernel_launch(void* const* d_in, const int* in_sizes, int n_in,
                              void* d_out, int out_size)
{
    const float* x   = (const float*)d_in[0];
    const float* wd1 = (const float*)d_in[1];
    const float* wd2 = (const float*)d_in[2];
    const float* wd3 = (const float*)d_in[3];
    const float* wo1 = (const float*)d_in[4];
    const float* wo2 = (const float*)d_in[5];
    const float* wo3 = (const float*)d_in[6];
    const float* bd1 = (const float*)d_in[7];
    const float* bd2 = (const float*)d_in[8];
    const float* bd3 = (const float*)d_in[9];
    const float* bo1 = (const float*)d_in[10];
    const float* bo2 = (const float*)d_in[11];
    const float* bo3 = (const float*)d_in[12];
    float* out = (float*)d_out;

    int nRows  = in_sizes[0] / 2;   // x is (B, 2)
    int nPairs = nRows / 2;         // 2 rows per thread
    int blocks = (nPairs + TPB - 1) / TPB;

    damping_kernel<<<blocks, TPB>>>(x, wd1, wd2, wd3, wo1, wo2, wo3,
                                    bd1, bd2, bd3, bo1, bo2, bo3,
                                    out, nPairs);
}

// round 10
// speedup vs baseline: 1.6731x; 1.5825x over previous
#include <cuda_runtime.h>
#include <cstdint>

#define H   32
#define TPB 128

typedef unsigned long long u64;

// ---------- packed f32x2 helpers ----------
__device__ __forceinline__ u64 pack2(float lo, float hi) {
    u64 r; asm("mov.b64 %0, {%1, %2};" : "=l"(r) : "f"(lo), "f"(hi)); return r;
}
__device__ __forceinline__ void unpack2(u64 v, float& lo, float& hi) {
    asm("mov.b64 {%0, %1}, %2;" : "=f"(lo), "=f"(hi) : "l"(v));
}
__device__ __forceinline__ u64 ffma2(u64 a, u64 b, u64 c) {
    u64 d; asm("fma.rn.f32x2 %0, %1, %2, %3;" : "=l"(d) : "l"(a), "l"(b), "l"(c)); return d;
}
__device__ __forceinline__ float tanh_mufu(float x) {
    float r; asm("tanh.approx.f32 %0, %1;" : "=f"(r) : "f"(x)); return r;
}
// tanh on a packed pair via MUFU.TANH: 2 MUFU + pack/unpack. Abs err ~4.9e-4.
__device__ __forceinline__ u64 tanh2(u64 v) {
    float lo, hi; unpack2(v, lo, hi);
    return pack2(tanh_mufu(lo), tanh_mufu(hi));
}

__device__ __forceinline__ u64 pairAB(float a, float b) {
    return ((u64)__float_as_uint(b) << 32) | (u64)__float_as_uint(a);
}

// Lane packing: lo half = d-network, hi half = o-network.
// Each thread processes TWO rows so every weight LDS feeds 4 FFMA2.
__global__ void __launch_bounds__(TPB)
damping_kernel(const float* __restrict__ x,
               const float* __restrict__ wd1, const float* __restrict__ wd2,
               const float* __restrict__ wd3, const float* __restrict__ wo1,
               const float* __restrict__ wo2, const float* __restrict__ wo3,
               const float* __restrict__ bd1, const float* __restrict__ bd2,
               const float* __restrict__ bd3, const float* __restrict__ bo1,
               const float* __restrict__ bo2, const float* __restrict__ bo3,
               float* __restrict__ out, int nPairs)
{
    __shared__ u64 s_w2[H * H];          // {wd2[j][k], wo2[j][k]}
    __shared__ u64 s_w1[2 * H];          // {wd1[i][k], wo1[i][k]}
    __shared__ u64 s_b1[H], s_b2[H];     // {bd*, bo*}
    __shared__ u64 s_w3a[H];             // {wd3[j][0], wo3[j][0]}
    __shared__ u64 s_w3b[H];             // {wd3[j][1], 0}
    __shared__ u64 s_p0, s_q0;           // {bd3[0], bo3[0]}, {bd3[1], 0}

    for (int i = threadIdx.x; i < H * H; i += TPB)
        s_w2[i] = pairAB(wd2[i], wo2[i]);
    for (int i = threadIdx.x; i < 2 * H; i += TPB)
        s_w1[i] = pairAB(wd1[i], wo1[i]);
    for (int i = threadIdx.x; i < H; i += TPB) {
        s_b1[i]  = pairAB(bd1[i], bo1[i]);
        s_b2[i]  = pairAB(bd2[i], bo2[i]);
        s_w3a[i] = pairAB(wd3[2 * i], wo3[i]);
        s_w3b[i] = pairAB(wd3[2 * i + 1], 0.0f);
    }
    if (threadIdx.x == 0) {
        s_p0 = pairAB(bd3[0], bo3[0]);
        s_q0 = pairAB(bd3[1], 0.0f);
    }
    __syncthreads();

    int pair = blockIdx.x * TPB + threadIdx.x;   // rows 2*pair, 2*pair+1
    if (pair >= nPairs) return;

    // x for 2 rows: {x0_r0, x1_r0, x0_r1, x1_r1}
    float4 xv = *reinterpret_cast<const float4*>(x + 4 * (size_t)pair);
    u64 X0a = pairAB(xv.x, xv.x), X1a = pairAB(xv.y, xv.y);
    u64 X0b = pairAB(xv.z, xv.z), X1b = pairAB(xv.w, xv.w);

    // ---- layer 1 (both rows, both nets packed per lane)
    u64 ha[H], hb[H];
    #pragma unroll
    for (int k = 0; k < H; k++) {
        u64 w0 = s_w1[k], w1 = s_w1[H + k], b = s_b1[k];
        ha[k] = tanh2(ffma2(X1a, w1, ffma2(X0a, w0, b)));
        hb[k] = tanh2(ffma2(X1b, w1, ffma2(X0b, w0, b)));
    }

    // ---- layer 2 + 3 fused; 8 accumulator chains (4 outputs x 2 rows)
    u64 Pa = s_p0, Qa = s_q0, Pb = s_p0, Qb = s_q0;
    #pragma unroll
    for (int kb = 0; kb < H; kb += 4) {
        u64 a0 = s_b2[kb], a1 = s_b2[kb + 1], a2 = s_b2[kb + 2], a3 = s_b2[kb + 3];
        u64 c0 = a0, c1 = a1, c2 = a2, c3 = a3;
        #pragma unroll
        for (int j = 0; j < H; j++) {
            const ulonglong2* wr = reinterpret_cast<const ulonglong2*>(s_w2 + j * H + kb);
            ulonglong2 w01 = wr[0];
            ulonglong2 w23 = wr[1];
            u64 hja = ha[j], hjb = hb[j];
            a0 = ffma2(hja, w01.x, a0);  c0 = ffma2(hjb, w01.x, c0);
            a1 = ffma2(hja, w01.y, a1);  c1 = ffma2(hjb, w01.y, c1);
            a2 = ffma2(hja, w23.x, a2);  c2 = ffma2(hjb, w23.x, c2);
            a3 = ffma2(hja, w23.y, a3);  c3 = ffma2(hjb, w23.y, c3);
        }
        a0 = tanh2(a0); a1 = tanh2(a1); a2 = tanh2(a2); a3 = tanh2(a3);
        c0 = tanh2(c0); c1 = tanh2(c1); c2 = tanh2(c2); c3 = tanh2(c3);
        u64 w3a0 = s_w3a[kb],     w3b0 = s_w3b[kb];
        u64 w3a1 = s_w3a[kb + 1], w3b1 = s_w3b[kb + 1];
        u64 w3a2 = s_w3a[kb + 2], w3b2 = s_w3b[kb + 2];
        u64 w3a3 = s_w3a[kb + 3], w3b3 = s_w3b[kb + 3];
        Pa = ffma2(a0, w3a0, Pa);  Qa = ffma2(a0, w3b0, Qa);
        Pb = ffma2(c0, w3a0, Pb);  Qb = ffma2(c0, w3b0, Qb);
        Pa = ffma2(a1, w3a1, Pa);  Qa = ffma2(a1, w3b1, Qa);
        Pb = ffma2(c1, w3a1, Pb);  Qb = ffma2(c1, w3b1, Qb);
        Pa = ffma2(a2, w3a2, Pa);  Qa = ffma2(a2, w3b2, Qa);
        Pb = ffma2(c2, w3a2, Pb);  Qb = ffma2(c2, w3b2, Qb);
        Pa = ffma2(a3, w3a3, Pa);  Qa = ffma2(a3, w3b3, Qa);
        Pb = ffma2(c3, w3a3, Pb);  Qb = ffma2(c3, w3b3, Qb);
    }

    // ---- epilogue, row a
    float d30, o3v, d31, junk;
    unpack2(Pa, d30, o3v);
    unpack2(Qa, d31, junk);
    float aa = (fmaxf(d30, 0.f) + 0.001f) * xv.x;
    float bb = (fmaxf(d31, 0.f) + 0.001f) * xv.y;
    float cc = o3v;
    float4 ov;
    ov.x = aa * aa * xv.x + aa * cc * xv.y;
    ov.y = aa * cc * xv.x + (cc * cc + bb * bb) * xv.y;

    // ---- epilogue, row b
    unpack2(Pb, d30, o3v);
    unpack2(Qb, d31, junk);
    aa = (fmaxf(d30, 0.f) + 0.001f) * xv.z;
    bb = (fmaxf(d31, 0.f) + 0.001f) * xv.w;
    cc = o3v;
    ov.z = aa * aa * xv.z + aa * cc * xv.w;
    ov.w = aa * cc * xv.z + (cc * cc + bb * bb) * xv.w;

    *reinterpret_cast<float4*>(out + 4 * (size_t)pair) = ov;
}

extern "C" void kernel_launch(void* const* d_in, const int* in_sizes, int n_in,
                              void* d_out, int out_size)
{
    const float* x   = (const float*)d_in[0];
    const float* wd1 = (const float*)d_in[1];
    const float* wd2 = (const float*)d_in[2];
    const float* wd3 = (const float*)d_in[3];
    const float* wo1 = (const float*)d_in[4];
    const float* wo2 = (const float*)d_in[5];
    const float* wo3 = (const float*)d_in[6];
    const float* bd1 = (const float*)d_in[7];
    const float* bd2 = (const float*)d_in[8];
    const float* bd3 = (const float*)d_in[9];
    const float* bo1 = (const float*)d_in[10];
    const float* bo2 = (const float*)d_in[11];
    const float* bo3 = (const float*)d_in[12];
    float* out = (float*)d_out;

    int nRows  = in_sizes[0] / 2;   // x is (B, 2)
    int nPairs = nRows / 2;         // 2 rows per thread
    int blocks = (nPairs + TPB - 1) / TPB;

    damping_kernel<<<blocks, TPB>>>(x, wd1, wd2, wd3, wo1, wo2, wo3,
                                    bd1, bd2, bd3, bo1, bo2, bo3,
                                    out, nPairs);
}